// round 12
// baseline (speedup 1.0000x reference)
#include <cuda_runtime.h>
#include <stdint.h>

// LSTM: H=50, input 1, T=1024, B independent batch elements.
// R=2 row-blocking x M=7 weight-shared batches, 2 blocks/SM:
// grid = ceil(2048/7) = 293 <= 148*2 = 296  ->  ONE full wave, no tail.
//   thread 2j   (even lane): rows j    (i-gate), j+100 (g-gate)
//   thread 2j+1 (odd  lane): rows j+50 (f-gate), j+150 (o-gate)
// Per thread per step: 91 broadcast LDS.128 + 364 fma.rn.f32x2 (14 chains)
// + 7 shfl. Even lane computes p = sig(i)*tanh(g); shfl_xor(1) hands it to
// the odd lane, which holds c privately and writes h (double-buffered).
// ONE __syncthreads per timestep. MUFU tanh.approx activations.
// Gate order (PyTorch): i[0:50], f[50:100], g[100:150], o[150:200].

#define HH 50
#define TT 1024
#define BT 128
#define MM 7
#define HSTRIDE 64    // padded h row (floats) for clean imm addressing

typedef unsigned long long ull;

__device__ __forceinline__ float tanha(float x) {
    float y;
    asm("tanh.approx.f32 %0, %1;" : "=f"(y) : "f"(x));
    return y;
}
__device__ __forceinline__ float sigt(float x) {
    return fmaf(0.5f, tanha(0.5f * x), 0.5f);   // sigmoid via tanh
}
__device__ __forceinline__ void fma2(ull& d, ull a, ull b) {
    asm("fma.rn.f32x2 %0, %1, %2, %0;" : "+l"(d) : "l"(a), "l"(b));
}
__device__ __forceinline__ ull pack2(float lo, float hi) {
    return ((ull)__float_as_uint(hi) << 32) | (ull)__float_as_uint(lo);
}
__device__ __forceinline__ float sum2(ull a) {
    return __uint_as_float((unsigned)a) + __uint_as_float((unsigned)(a >> 32));
}

__global__ void __launch_bounds__(BT, 2)
lstm_kernel(const float* __restrict__ x,      // [B, T, 1]
            const float* __restrict__ W_ih,   // [200, 1]
            const float* __restrict__ W_hh,   // [200, 50]
            const float* __restrict__ b_ih,   // [200]
            const float* __restrict__ b_hh,   // [200]
            const float* __restrict__ W_lin,  // [1, 50]
            const float* __restrict__ b_lin,  // [1]
            float* __restrict__ out,          // [B, 1]
            int B)
{
    __shared__ __align__(16) float h_sh[2][MM][HSTRIDE];  // [buf][batch][idx]
    __shared__ float x_sh[MM][TT];

    const int tid = threadIdx.x;
    const int b0  = blockIdx.x * MM;
    const int jj  = tid >> 1;            // hidden index 0..63
    const int odd = tid & 1;             // 0: (i,g)   1: (f,o)
    const bool active = (jj < HH);

    for (int i = tid; i < MM * TT; i += BT) {
        const int m = i / TT, t = i & (TT - 1);
        x_sh[m][t] = (b0 + m < B) ? x[(size_t)(b0 + m) * TT + t] : 0.0f;
    }
    for (int i = tid; i < 2 * MM * HSTRIDE; i += BT) ((float*)h_sh)[i] = 0.0f;

    // Rows: rA = i or f, rB = g or o (zero weights if inactive).
    const int rA = jj + odd * 50;
    const int rB = rA + 100;
    ull wA[26], wB[26];
    float wihA = 0.0f, wihB = 0.0f, biasA = 0.0f, biasB = 0.0f;
    if (active) {
        wihA  = W_ih[rA];            wihB  = W_ih[rB];
        biasA = b_ih[rA] + b_hh[rA]; biasB = b_ih[rB] + b_hh[rB];
    }
    #pragma unroll
    for (int q = 0; q < 26; q++) {
        float l0 = (active && 2 * q     < HH) ? W_hh[rA * HH + 2 * q]     : 0.0f;
        float l1 = (active && 2 * q + 1 < HH) ? W_hh[rA * HH + 2 * q + 1] : 0.0f;
        float m0 = (active && 2 * q     < HH) ? W_hh[rB * HH + 2 * q]     : 0.0f;
        float m1 = (active && 2 * q + 1 < HH) ? W_hh[rB * HH + 2 * q + 1] : 0.0f;
        wA[q] = pack2(l0, l1);
        wB[q] = pack2(m0, m1);
    }
    float c[MM];
    #pragma unroll
    for (int m = 0; m < MM; m++) c[m] = 0.0f;    // cell state, odd lanes
    __syncthreads();

    #pragma unroll 1
    for (int t = 0; t < TT; t++) {
        const int rb = t & 1;
        ull aA[MM], aB[MM];
        #pragma unroll
        for (int m = 0; m < MM; m++) {
            const float xt = x_sh[m][t];
            aA[m] = (ull)__float_as_uint(fmaf(xt, wihA, biasA));  // hi = +0
            aB[m] = (ull)__float_as_uint(fmaf(xt, wihB, biasB));
        }
        // Single base pointer; per-(m,q) offsets are immediates.
        const ulonglong2* hb = (const ulonglong2*)h_sh[rb];
        #pragma unroll
        for (int q = 0; q < 13; q++) {
            #pragma unroll
            for (int m = 0; m < MM; m++) {
                ulonglong2 hv = hb[m * (HSTRIDE / 4) + q];   // broadcast LDS.128
                fma2(aA[m], wA[2 * q],     hv.x);            // folded chains
                fma2(aA[m], wA[2 * q + 1], hv.y);
                fma2(aB[m], wB[2 * q],     hv.x);
                fma2(aB[m], wB[2 * q + 1], hv.y);
            }
        }
        float* hw = &h_sh[rb ^ 1][0][jj];
        #pragma unroll
        for (int m = 0; m < MM; m++) {
            const float sA = sum2(aA[m]);          // i or f
            const float sB = sum2(aB[m]);          // g or o
            const float act0 = sigt(sA);                       // sig(i)/sig(f)
            const float act1 = odd ? sigt(sB) : tanha(sB);     // sig(o)/tanh(g)
            const float p = act0 * act1;           // even lane: sig(i)*tanh(g)
            const float q2 = __shfl_xor_sync(0xFFFFFFFFu, p, 1);
            if (odd & (int)active) {
                c[m] = fmaf(act0, c[m], q2);       // sig(f)*c + sig(i)*tanh(g)
                hw[m * HSTRIDE] = act1 * tanha(c[m]);   // sig(o)*tanh(c)
            }
        }
        __syncthreads();
    }

    // Final h in buffer (1023&1)^1 == 0. Linear head, one thread per batch.
    if (tid < MM && b0 + tid < B) {
        float s = b_lin[0];
        #pragma unroll 1
        for (int k = 0; k < HH; k++) s = fmaf(h_sh[0][tid][k], W_lin[k], s);
        out[b0 + tid] = s;
    }
}

extern "C" void kernel_launch(void* const* d_in, const int* in_sizes, int n_in,
                              void* d_out, int out_size) {
    const float* x     = (const float*)d_in[0];
    const float* W_ih  = (const float*)d_in[1];
    const float* W_hh  = (const float*)d_in[2];
    const float* b_ih  = (const float*)d_in[3];
    const float* b_hh  = (const float*)d_in[4];
    const float* W_lin = (const float*)d_in[5];
    const float* b_lin = (const float*)d_in[6];
    float* out = (float*)d_out;

    int B = in_sizes[0] / TT;
    int grid = (B + MM - 1) / MM;
    lstm_kernel<<<grid, BT>>>(x, W_ih, W_hh, b_ih, b_hh, W_lin, b_lin, out, B);
}